// round 6
// baseline (speedup 1.0000x reference)
#include <cuda_runtime.h>
#include <cuda_bf16.h>
#include <math.h>
#include <stdint.h>

#define BB 4
#define SS 8192
#define EE 1024
#define HH 16
#define DD 64
#define LL 64
#define NCAND 96
#define MROWS (BB * SS)
#define MSZ   ((size_t)MROWS * EE)

// ===================== scratch ==============================================
__device__ float g_Q[MSZ];
__device__ float g_K[MSZ];
__device__ float g_ctx[MSZ];
__device__ __nv_bfloat16 g_Ahi[MSZ];
__device__ __nv_bfloat16 g_Amid[MSZ];
__device__ __nv_bfloat16 g_Whi[EE * EE];
__device__ __nv_bfloat16 g_Wmid[EE * EE];
__device__ float g_scores[BB * SS];
__device__ int   g_idx96[BB * NCAND];
__device__ float g_kex[BB * NCAND * EE];
__device__ float g_vex[BB * NCAND * EE];
__device__ float g_scex[BB * NCAND];
__device__ int   g_idxf[BB * LL];
__device__ int   g_candf[BB * LL];
__device__ float g_Ksp[BB * HH * LL * DD];
__device__ float g_Vsp[BB * HH * LL * DD];

// ===================== small PTX helpers ====================================
__device__ __forceinline__ uint32_t smem_u32(const void* p) {
    uint32_t a;
    asm("{ .reg .u64 t; cvta.to.shared.u64 t, %1; cvt.u32.u64 %0, t; }" : "=r"(a) : "l"(p));
    return a;
}
__device__ __forceinline__ void cp16(uint32_t dst, const void* src) {
    asm volatile("cp.async.cg.shared.global [%0], [%1], 16;" :: "r"(dst), "l"(src));
}
#define CP_COMMIT() asm volatile("cp.async.commit_group;" ::: "memory")
#define CP_WAIT1()  asm volatile("cp.async.wait_group 1;" ::: "memory")
__device__ __forceinline__ void ldm_x4(uint32_t* r, uint32_t addr) {
    asm volatile("ldmatrix.sync.aligned.m8n8.x4.shared.b16 {%0,%1,%2,%3}, [%4];"
                 : "=r"(r[0]), "=r"(r[1]), "=r"(r[2]), "=r"(r[3]) : "r"(addr));
}
#define MMA16816(d, a, b0, b1) \
    asm volatile("mma.sync.aligned.m16n8k16.row.col.f32.bf16.bf16.f32 " \
        "{%0,%1,%2,%3}, {%4,%5,%6,%7}, {%8,%9}, {%0,%1,%2,%3};" \
        : "+f"((d)[0]), "+f"((d)[1]), "+f"((d)[2]), "+f"((d)[3]) \
        : "r"((a)[0]), "r"((a)[1]), "r"((a)[2]), "r"((a)[3]), \
          "r"(b0), "r"(b1))

// ===================== fp32 -> (hi, mid) bf16 split =========================
__global__ __launch_bounds__(256) void split2_kernel(
    const float* __restrict__ x, __nv_bfloat16* __restrict__ hi,
    __nv_bfloat16* __restrict__ mid, int n4)
{
    int i = blockIdx.x * 256 + threadIdx.x;
    if (i >= n4) return;
    float4 v = ((const float4*)x)[i];
    float vv[4] = {v.x, v.y, v.z, v.w};
    uint32_t hb[4], mb[4];
    #pragma unroll
    for (int q = 0; q < 4; q++) {
        __nv_bfloat16 h = __float2bfloat16(vv[q]);
        __nv_bfloat16 m = __float2bfloat16(vv[q] - __bfloat162float(h));
        hb[q] = (uint32_t)__bfloat16_as_ushort(h);
        mb[q] = (uint32_t)__bfloat16_as_ushort(m);
    }
    uint2 hp, mp;
    hp.x = hb[0] | (hb[1] << 16); hp.y = hb[2] | (hb[3] << 16);
    mp.x = mb[0] | (mb[1] << 16); mp.y = mb[2] | (mb[3] << 16);
    ((uint2*)hi)[i] = hp;
    ((uint2*)mid)[i] = mp;
}

// ===================== HMMA split-bf16 GEMM =================================
// BM=128, BN=256, BK=64, 256 thr, warp grid 2(M)x4(N), warp tile 64x64.
// 3-stage cp.async pipeline, 48KB/stage. Swizzle chunk c^(row&7).

#define GSTAGE 49152u
#define GEMM_SMEM (3 * 49152)
#define NKT 48

__global__ __launch_bounds__(256) void mma_gemm(
    const __nv_bfloat16* __restrict__ Ahi, const __nv_bfloat16* __restrict__ Amid,
    const __nv_bfloat16* __restrict__ Whi, const __nv_bfloat16* __restrict__ Wmid,
    const float* __restrict__ bias, float* __restrict__ C)
{
    extern __shared__ __align__(128) char dsm[];
    const uint32_t sbase = smem_u32(dsm);

    const int tid  = threadIdx.x;
    const int lane = tid & 31;
    const int wid  = tid >> 5;
    const int bm = blockIdx.y * 128;
    const int bn = blockIdx.x * 256;
    const int m0 = (wid & 1) * 64;
    const int n0 = (wid >> 1) * 64;
    const int qrow = lane >> 2;
    const int qk   = (lane & 3) * 2;
    const int lrow  = lane & 7;
    const int phase = lane >> 3;

    const __nv_bfloat16* Aregs[3] = {Ahi, Amid, Ahi};
    const __nv_bfloat16* Wregs[3] = {Whi, Whi, Wmid};

    const int g_c  = tid & 7;
    const int g_r0 = tid >> 3;          // 0..31

    float c[4][8][4];
    #pragma unroll
    for (int mt = 0; mt < 4; mt++)
        #pragma unroll
        for (int nt = 0; nt < 8; nt++)
            #pragma unroll
            for (int q = 0; q < 4; q++) c[mt][nt][q] = 0.f;

    auto load_tile = [&](int kt) {
        if (kt < NKT) {
            const int stage = kt % 3;
            const uint32_t sA = sbase + (uint32_t)stage * GSTAGE;
            const uint32_t sB = sA + 16384u;
            const int reg = kt >> 4;
            const int kk  = (kt & 15) << 6;
            const __nv_bfloat16* Ag = Aregs[reg];
            const __nv_bfloat16* Wg = Wregs[reg];
            #pragma unroll
            for (int i = 0; i < 4; i++) {
                int row = g_r0 + i * 32;
                uint32_t off = (uint32_t)(row * 128 + ((g_c ^ (row & 7)) << 4));
                cp16(sA + off, Ag + (size_t)(bm + row) * 1024 + kk + g_c * 8);
            }
            #pragma unroll
            for (int i = 0; i < 8; i++) {
                int row = g_r0 + i * 32;
                uint32_t off = (uint32_t)(row * 128 + ((g_c ^ (row & 7)) << 4));
                cp16(sB + off, Wg + (size_t)(bn + row) * 1024 + kk + g_c * 8);
            }
        }
        CP_COMMIT();
    };

    load_tile(0);
    load_tile(1);

    for (int kt = 0; kt < NKT; kt++) {
        CP_WAIT1();
        __syncthreads();
        load_tile(kt + 2);

        const uint32_t aB = sbase + (uint32_t)(kt % 3) * GSTAGE;
        const uint32_t bB = aB + 16384u;

        #pragma unroll
        for (int ks = 0; ks < 4; ks++) {
            const int c0 = ks * 2;
            uint32_t a[4][4];
            #pragma unroll
            for (int mt = 0; mt < 4; mt++) {
                int row = m0 + mt * 16 + (phase & 1) * 8 + lrow;
                int ch  = c0 + (phase >> 1);
                ldm_x4(a[mt], aB + (uint32_t)(row * 128 + ((ch ^ (row & 7)) << 4)));
            }
            uint32_t bf[4][4];
            #pragma unroll
            for (int ng = 0; ng < 4; ng++) {
                int row = n0 + ng * 16 + (phase >> 1) * 8 + lrow;
                int ch  = c0 + (phase & 1);
                ldm_x4(bf[ng], bB + (uint32_t)(row * 128 + ((ch ^ (row & 7)) << 4)));
            }
            #pragma unroll
            for (int nt = 0; nt < 8; nt++) {
                uint32_t b0 = bf[nt >> 1][(nt & 1) * 2];
                uint32_t b1 = bf[nt >> 1][(nt & 1) * 2 + 1];
                #pragma unroll
                for (int mt = 0; mt < 4; mt++)
                    MMA16816(c[mt][nt], a[mt], b0, b1);
            }
        }
        __syncthreads();
    }

    // ---- epilogue ----
    #pragma unroll
    for (int mt = 0; mt < 4; mt++) {
        #pragma unroll
        for (int nt = 0; nt < 8; nt++) {
            int r0  = bm + m0 + mt * 16 + qrow;
            int col = bn + n0 + nt * 8 + qk;
            float2 bv = *(const float2*)(bias + col);
            float2 o0, o1;
            o0.x = c[mt][nt][0] + bv.x; o0.y = c[mt][nt][1] + bv.y;
            o1.x = c[mt][nt][2] + bv.x; o1.y = c[mt][nt][3] + bv.y;
            *(float2*)(C + (size_t)r0 * 1024 + col) = o0;
            *(float2*)(C + (size_t)(r0 + 8) * 1024 + col) = o1;
        }
    }
}

// ===================== scores[row] = mean_h ||X[row, h*64:+64]|| ============
__global__ __launch_bounds__(256) void scores_kernel(
    const float* __restrict__ Km, float* __restrict__ scores)
{
    int row  = blockIdx.x * 8 + (threadIdx.x >> 5);
    int lane = threadIdx.x & 31;
    const float* kr = Km + (size_t)row * EE;
    float acc = 0.f;
    #pragma unroll
    for (int h = 0; h < HH; h++) {
        float x0 = kr[h * 64 + lane];
        float x1 = kr[h * 64 + 32 + lane];
        float ss = x0 * x0 + x1 * x1;
        #pragma unroll
        for (int o = 16; o > 0; o >>= 1)
            ss += __shfl_xor_sync(0xffffffffu, ss, o);
        acc += sqrtf(ss);
    }
    if (lane == 0) scores[row] = acc * (1.f / 16.f);
}

// ===================== approx top-kk per batch (1024 threads) ===============
__global__ __launch_bounds__(1024) void topk_kernel(
    const float* __restrict__ scores, int* __restrict__ idxout, int kk)
{
    __shared__ float sv[SS];
    __shared__ float rv[1024];
    __shared__ int   ri[1024];
    const int b = blockIdx.x, t = threadIdx.x;
    for (int i = t; i < SS; i += 1024) sv[i] = scores[b * SS + i];
    __syncthreads();
    for (int l = 0; l < kk; l++) {
        float m = -INFINITY; int a = 0;
        #pragma unroll
        for (int u = 0; u < 8; u++) {
            int i = t + u * 1024;
            float v = sv[i];
            if (v > m) { m = v; a = i; }
        }
        rv[t] = m; ri[t] = a;
        __syncthreads();
        for (int s = 512; s > 0; s >>= 1) {
            if (t < s) {
                float v2 = rv[t + s]; int a2 = ri[t + s];
                if (v2 > rv[t] || (v2 == rv[t] && a2 < ri[t])) { rv[t] = v2; ri[t] = a2; }
            }
            __syncthreads();
        }
        if (t == 0) { idxout[b * kk + l] = ri[0]; sv[ri[0]] = -INFINITY; }
        __syncthreads();
    }
}

// ===================== exact fp32 projection of candidate rows ==============
template<int CPT>
__global__ __launch_bounds__(256) void project_rows(
    const float* __restrict__ X, const float* __restrict__ Wt,
    const float* __restrict__ bias, const int* __restrict__ idx,
    int ncand, float* __restrict__ outp)
{
    __shared__ float xs[NCAND * 32];
    __shared__ float ws[32 * 128];
    const int b = blockIdx.y;
    const int e0 = blockIdx.x * 128;
    const int t = threadIdx.x, tx = t & 31, ty = t >> 5;

    float acc[CPT][4];
    #pragma unroll
    for (int c = 0; c < CPT; c++)
        #pragma unroll
        for (int j = 0; j < 4; j++) acc[c][j] = 0.f;

    for (int kt = 0; kt < EE; kt += 32) {
        __syncthreads();
        for (int u = t; u < ncand * 8; u += 256) {
            int cand = u >> 3, c4 = u & 7;
            int s = idx[b * ncand + cand];
            float4 v = *(const float4*)(X + ((size_t)(b * SS + s)) * EE + kt + c4 * 4);
            *(float4*)(xs + cand * 32 + c4 * 4) = v;
        }
        for (int u = t; u < 1024; u += 256) {
            int e = u >> 3, c4 = u & 7;
            float4 v = *(const float4*)(Wt + (size_t)(e0 + e) * EE + kt + c4 * 4);
            ws[(c4 * 4 + 0) * 128 + e] = v.x;
            ws[(c4 * 4 + 1) * 128 + e] = v.y;
            ws[(c4 * 4 + 2) * 128 + e] = v.z;
            ws[(c4 * 4 + 3) * 128 + e] = v.w;
        }
        __syncthreads();
        #pragma unroll 8
        for (int k = 0; k < 32; k++) {
            float wv[4];
            #pragma unroll
            for (int j = 0; j < 4; j++) wv[j] = ws[k * 128 + tx * 4 + j];
            #pragma unroll
            for (int c = 0; c < CPT; c++) {
                float a = xs[(ty * CPT + c) * 32 + k];
                #pragma unroll
                for (int j = 0; j < 4; j++) acc[c][j] = fmaf(a, wv[j], acc[c][j]);
            }
        }
    }
    #pragma unroll
    for (int c = 0; c < CPT; c++) {
        int cand = ty * CPT + c;
        #pragma unroll
        for (int j = 0; j < 4; j++) {
            int e = e0 + tx * 4 + j;
            outp[((size_t)b * ncand + cand) * EE + e] = acc[c][j] + bias[e];
        }
    }
}

// ===================== exact top-64 among the 96 candidates =================
__global__ __launch_bounds__(128) void topk_refine_kernel(
    const float* __restrict__ scex, const int* __restrict__ idx96,
    int* __restrict__ idxfin, int* __restrict__ candfin)
{
    __shared__ float sv[NCAND];
    __shared__ int   si[NCAND];
    __shared__ float rv[128];
    __shared__ int   rc[128];
    __shared__ int   rs[128];
    const int b = blockIdx.x, t = threadIdx.x;
    if (t < NCAND) { sv[t] = scex[b * NCAND + t]; si[t] = idx96[b * NCAND + t]; }
    __syncthreads();
    for (int l = 0; l < LL; l++) {
        float m = -INFINITY; int c = 0; int sb = 0x7fffffff;
        if (t < NCAND) { m = sv[t]; c = t; sb = si[t]; }
        rv[t] = m; rc[t] = c; rs[t] = sb;
        __syncthreads();
        for (int s = 64; s > 0; s >>= 1) {
            if (t < s) {
                if (rv[t + s] > rv[t] || (rv[t + s] == rv[t] && rs[t + s] < rs[t])) {
                    rv[t] = rv[t + s]; rc[t] = rc[t + s]; rs[t] = rs[t + s];
                }
            }
            __syncthreads();
        }
        if (t == 0) {
            idxfin[b * LL + l] = rs[0];
            candfin[b * LL + l] = rc[0];
            sv[rc[0]] = -INFINITY;
        }
        __syncthreads();
    }
}

// ===================== permute exact rows into [B,H,L,D] ====================
__global__ __launch_bounds__(256) void gatherperm_kernel(
    const float* __restrict__ kex, const float* __restrict__ vex,
    const int* __restrict__ candf,
    float* __restrict__ Ksp, float* __restrict__ Vsp)
{
    int i = blockIdx.x * 256 + threadIdx.x;
    int d = i & 63;
    int l = (i >> 6) & 63;
    int h = (i >> 12) & 15;
    int b = i >> 16;
    int cp = candf[b * LL + l];
    size_t src = ((size_t)b * NCAND + cp) * EE + h * 64 + d;
    Ksp[i] = kex[src];
    Vsp[i] = vex[src];
}

// ===================== attention (128 thr, 2 chunks, coalesced w) ===========
#define ATTN_SMEM ((4096 + 4096 + 8192 + 128) * 4)
__global__ __launch_bounds__(128) void attn_kernel(
    const float* __restrict__ Q, const float* __restrict__ Ksp,
    const float* __restrict__ Vsp, float* __restrict__ w_out,
    float* __restrict__ ctx)
{
    extern __shared__ float asm_[];
    float* Kt  = asm_;            // 64x64
    float* Vt  = asm_ + 4096;     // 64x64
    float* sc  = asm_ + 8192;     // [l][i] 64x128
    float* inv = asm_ + 16384;    // 128

    const int b = blockIdx.z, h = blockIdx.y, chunk = blockIdx.x;
    const int i = threadIdx.x;    // 0..127

    const float* Kg = Ksp + ((size_t)(b * HH + h) << 12);
    const float* Vg = Vsp + ((size_t)(b * HH + h) << 12);
    #pragma unroll
    for (int j = 0; j < 8; j++) {
        ((float4*)Kt)[i + j * 128] = ((const float4*)Kg)[i + j * 128];
        ((float4*)Vt)[i + j * 128] = ((const float4*)Vg)[i + j * 128];
    }
    __syncthreads();

    const int s = chunk * 128 + i;
    const float* qp = Q + ((size_t)(b * SS + s)) * EE + h * 64;
    float4 q4[16];
    #pragma unroll
    for (int j = 0; j < 16; j++) q4[j] = ((const float4*)qp)[j];

    float mx = -INFINITY;
    #pragma unroll 4
    for (int l = 0; l < 64; l++) {
        const float4* kl = (const float4*)(Kt + l * 64);
        float acc = 0.f;
        #pragma unroll
        for (int j = 0; j < 16; j++) {
            float4 kv = kl[j];
            acc = fmaf(q4[j].x, kv.x, acc);
            acc = fmaf(q4[j].y, kv.y, acc);
            acc = fmaf(q4[j].z, kv.z, acc);
            acc = fmaf(q4[j].w, kv.w, acc);
        }
        acc *= 0.125f;
        sc[l * 128 + i] = acc;
        mx = fmaxf(mx, acc);
    }

    float sum = 0.f;
    #pragma unroll 4
    for (int l = 0; l < 64; l++) {
        float e = expf(sc[l * 128 + i] - mx);
        sc[l * 128 + i] = e;
        sum += e;
    }
    const float myinv = 1.f / sum;
    inv[i] = myinv;

    // ctx accumulation (uses own column of sc)
    float4 c4[16];
    #pragma unroll
    for (int j = 0; j < 16; j++) c4[j] = make_float4(0.f, 0.f, 0.f, 0.f);
    #pragma unroll 2
    for (int l = 0; l < 64; l++) {
        float wl = sc[l * 128 + i] * myinv;
        const float4* vl = (const float4*)(Vt + l * 64);
        #pragma unroll
        for (int j = 0; j < 16; j++) {
            float4 vv = vl[j];
            c4[j].x = fmaf(wl, vv.x, c4[j].x);
            c4[j].y = fmaf(wl, vv.y, c4[j].y);
            c4[j].z = fmaf(wl, vv.z, c4[j].z);
            c4[j].w = fmaf(wl, vv.w, c4[j].w);
        }
    }
    float* cp = ctx + ((size_t)(b * SS + s)) * EE + h * 64;
    #pragma unroll
    for (int j = 0; j < 16; j++) ((float4*)cp)[j] = c4[j];

    __syncthreads();
    // coalesced w write: w[b,h, chunk*128+sl, l]
    float* wbase = w_out + ((size_t)((b * HH + h) * SS + chunk * 128)) * LL;
    #pragma unroll
    for (int u0 = 0; u0 < 64; u0++) {
        int u = i + u0 * 128;
        int sl = u >> 6, l = u & 63;
        wbase[u] = sc[l * 128 + sl] * inv[sl];
    }
}

// ===================== launch ===============================================
extern "C" void kernel_launch(void* const* d_in, const int* in_sizes, int n_in,
                              void* d_out, int out_size)
{
    const float* query = (const float*)d_in[0];
    const float* key   = (const float*)d_in[1];
    const float* value = (const float*)d_in[2];
    const float* Wq = (const float*)d_in[3];
    const float* bq = (const float*)d_in[4];
    const float* Wk = (const float*)d_in[5];
    const float* bk = (const float*)d_in[6];
    const float* Wv = (const float*)d_in[7];
    const float* bv = (const float*)d_in[8];
    const float* Wo = (const float*)d_in[9];
    const float* bo = (const float*)d_in[10];

    float* out  = (float*)d_out;
    float* wout = out + MSZ;

    float *pQ, *pK, *pC, *pScores, *pKex, *pVex, *pScex, *pKsp, *pVsp;
    __nv_bfloat16 *pAhi, *pAmid, *pWhi, *pWmid;
    int *pIdx96, *pIdxf, *pCandf;
    cudaGetSymbolAddress((void**)&pQ, g_Q);
    cudaGetSymbolAddress((void**)&pK, g_K);
    cudaGetSymbolAddress((void**)&pC, g_ctx);
    cudaGetSymbolAddress((void**)&pAhi, g_Ahi);
    cudaGetSymbolAddress((void**)&pAmid, g_Amid);
    cudaGetSymbolAddress((void**)&pWhi, g_Whi);
    cudaGetSymbolAddress((void**)&pWmid, g_Wmid);
    cudaGetSymbolAddress((void**)&pScores, g_scores);
    cudaGetSymbolAddress((void**)&pIdx96, g_idx96);
    cudaGetSymbolAddress((void**)&pKex, g_kex);
    cudaGetSymbolAddress((void**)&pVex, g_vex);
    cudaGetSymbolAddress((void**)&pScex, g_scex);
    cudaGetSymbolAddress((void**)&pIdxf, g_idxf);
    cudaGetSymbolAddress((void**)&pCandf, g_candf);
    cudaGetSymbolAddress((void**)&pKsp, g_Ksp);
    cudaGetSymbolAddress((void**)&pVsp, g_Vsp);

    cudaFuncSetAttribute(mma_gemm, cudaFuncAttributeMaxDynamicSharedMemorySize, GEMM_SMEM);
    cudaFuncSetAttribute(attn_kernel, cudaFuncAttributeMaxDynamicSharedMemorySize, ATTN_SMEM);

    const int n4m = (int)(MSZ / 4);
    const int n4w = EE * EE / 4;
    dim3 ggrid(4, 256);            // BN=256 -> 4 col-blocks, BM=128 -> 256 row-blocks

    // Q = query @ Wq^T + bq
    split2_kernel<<<n4m / 256, 256>>>(query, pAhi, pAmid, n4m);
    split2_kernel<<<n4w / 256, 256>>>(Wq, pWhi, pWmid, n4w);
    mma_gemm<<<ggrid, 256, GEMM_SMEM>>>(pAhi, pAmid, pWhi, pWmid, bq, pQ);

    // K = key @ Wk^T + bk
    split2_kernel<<<n4m / 256, 256>>>(key, pAhi, pAmid, n4m);
    split2_kernel<<<n4w / 256, 256>>>(Wk, pWhi, pWmid, n4w);
    mma_gemm<<<ggrid, 256, GEMM_SMEM>>>(pAhi, pAmid, pWhi, pWmid, bk, pK);

    // approx scores -> top-96 candidates
    scores_kernel<<<MROWS / 8, 256>>>(pK, pScores);
    topk_kernel<<<BB, 1024>>>(pScores, pIdx96, NCAND);

    // exact fp32 K/V rows at candidates, exact scores, exact top-64
    dim3 pgrid(8, BB);
    project_rows<12><<<pgrid, 256>>>(key,   Wk, bk, pIdx96, NCAND, pKex);
    project_rows<12><<<pgrid, 256>>>(value, Wv, bv, pIdx96, NCAND, pVex);
    scores_kernel<<<(BB * NCAND) / 8, 256>>>(pKex, pScex);
    topk_refine_kernel<<<BB, 128>>>(pScex, pIdx96, pIdxf, pCandf);
    gatherperm_kernel<<<(BB * HH * LL * DD) / 256, 256>>>(pKex, pVex, pCandf, pKsp, pVsp);

    // attention
    dim3 agrid(SS / 128, HH, BB);
    attn_kernel<<<agrid, 128, ATTN_SMEM>>>(pQ, pKsp, pVsp, wout, pC);

    // out = ctx @ Wo^T + bo
    split2_kernel<<<n4m / 256, 256>>>(pC, pAhi, pAmid, n4m);
    split2_kernel<<<n4w / 256, 256>>>(Wo, pWhi, pWmid, n4w);
    mma_gemm<<<ggrid, 256, GEMM_SMEM>>>(pAhi, pAmid, pWhi, pWmid, bo, out);
}

// round 7
// speedup vs baseline: 1.1108x; 1.1108x over previous
#include <cuda_runtime.h>
#include <cuda_bf16.h>
#include <math.h>
#include <stdint.h>

#define BB 4
#define SS 8192
#define EE 1024
#define HH 16
#define DD 64
#define LL 64
#define NCAND 96
#define MROWS (BB * SS)
#define MSZ   ((size_t)MROWS * EE)

// ===================== scratch ==============================================
__device__ float g_Q[MSZ];
__device__ float g_K[MSZ];
__device__ float g_ctx[MSZ];
__device__ __nv_bfloat16 g_Aqhi[MSZ];
__device__ __nv_bfloat16 g_Aqmid[MSZ];
__device__ __nv_bfloat16 g_Akhi[MSZ];
__device__ __nv_bfloat16 g_Akmid[MSZ];
__device__ __nv_bfloat16 g_Wqhi[EE * EE];
__device__ __nv_bfloat16 g_Wqmid[EE * EE];
__device__ __nv_bfloat16 g_Wkhi[EE * EE];
__device__ __nv_bfloat16 g_Wkmid[EE * EE];
__device__ __nv_bfloat16 g_Wohi[EE * EE];
__device__ __nv_bfloat16 g_Womid[EE * EE];
__device__ float g_scores[BB * SS];
__device__ int   g_idx96[BB * NCAND];
__device__ float g_kex[BB * NCAND * EE];
__device__ float g_vex[BB * NCAND * EE];
__device__ float g_scex[BB * NCAND];
__device__ int   g_idxf[BB * LL];
__device__ int   g_candf[BB * LL];
__device__ float g_Ksp[BB * HH * LL * DD];
__device__ float g_Vsp[BB * HH * LL * DD];

// ===================== small PTX helpers ====================================
__device__ __forceinline__ uint32_t smem_u32(const void* p) {
    uint32_t a;
    asm("{ .reg .u64 t; cvta.to.shared.u64 t, %1; cvt.u32.u64 %0, t; }" : "=r"(a) : "l"(p));
    return a;
}
__device__ __forceinline__ void cp16(uint32_t dst, const void* src) {
    asm volatile("cp.async.cg.shared.global [%0], [%1], 16;" :: "r"(dst), "l"(src));
}
#define CP_COMMIT() asm volatile("cp.async.commit_group;" ::: "memory")
#define CP_WAIT1()  asm volatile("cp.async.wait_group 1;" ::: "memory")
__device__ __forceinline__ void ldm_x4(uint32_t* r, uint32_t addr) {
    asm volatile("ldmatrix.sync.aligned.m8n8.x4.shared.b16 {%0,%1,%2,%3}, [%4];"
                 : "=r"(r[0]), "=r"(r[1]), "=r"(r[2]), "=r"(r[3]) : "r"(addr));
}
#define MMA16816(d, a, b0, b1) \
    asm volatile("mma.sync.aligned.m16n8k16.row.col.f32.bf16.bf16.f32 " \
        "{%0,%1,%2,%3}, {%4,%5,%6,%7}, {%8,%9}, {%0,%1,%2,%3};" \
        : "+f"((d)[0]), "+f"((d)[1]), "+f"((d)[2]), "+f"((d)[3]) \
        : "r"((a)[0]), "r"((a)[1]), "r"((a)[2]), "r"((a)[3]), \
          "r"(b0), "r"(b1))

// ===================== fp32 -> (hi, mid) bf16 split =========================
__global__ __launch_bounds__(256) void split2_kernel(
    const float* __restrict__ x, __nv_bfloat16* __restrict__ hi,
    __nv_bfloat16* __restrict__ mid, int n4)
{
    int i = blockIdx.x * 256 + threadIdx.x;
    if (i >= n4) return;
    float4 v = ((const float4*)x)[i];
    float vv[4] = {v.x, v.y, v.z, v.w};
    uint32_t hb[4], mb[4];
    #pragma unroll
    for (int q = 0; q < 4; q++) {
        __nv_bfloat16 h = __float2bfloat16(vv[q]);
        __nv_bfloat16 m = __float2bfloat16(vv[q] - __bfloat162float(h));
        hb[q] = (uint32_t)__bfloat16_as_ushort(h);
        mb[q] = (uint32_t)__bfloat16_as_ushort(m);
    }
    uint2 hp, mp;
    hp.x = hb[0] | (hb[1] << 16); hp.y = hb[2] | (hb[3] << 16);
    mp.x = mb[0] | (mb[1] << 16); mp.y = mb[2] | (mb[3] << 16);
    ((uint2*)hi)[i] = hp;
    ((uint2*)mid)[i] = mp;
}

// ===================== HMMA split-bf16 GEMM =================================
// BM=128, BN=256, BK=64, 256 thr, warp grid 2(M)x4(N), warp tile 64x64.
// NKT=48: 3 products (hi*hi, mid*hi, hi*mid). NKT=16: single product hi*hi.

#define GSTAGE 49152u
#define GEMM_SMEM (3 * 49152)

template<int NKT>
__global__ __launch_bounds__(256) void mma_gemm(
    const __nv_bfloat16* __restrict__ Ahi, const __nv_bfloat16* __restrict__ Amid,
    const __nv_bfloat16* __restrict__ Whi, const __nv_bfloat16* __restrict__ Wmid,
    const float* __restrict__ bias, float* __restrict__ C)
{
    extern __shared__ __align__(128) char dsm[];
    const uint32_t sbase = smem_u32(dsm);

    const int tid  = threadIdx.x;
    const int lane = tid & 31;
    const int wid  = tid >> 5;
    const int bm = blockIdx.y * 128;
    const int bn = blockIdx.x * 256;
    const int m0 = (wid & 1) * 64;
    const int n0 = (wid >> 1) * 64;
    const int qrow = lane >> 2;
    const int qk   = (lane & 3) * 2;
    const int lrow  = lane & 7;
    const int phase = lane >> 3;

    const __nv_bfloat16* Aregs[3] = {Ahi, Amid, Ahi};
    const __nv_bfloat16* Wregs[3] = {Whi, Whi, Wmid};

    const int g_c  = tid & 7;
    const int g_r0 = tid >> 3;          // 0..31

    float c[4][8][4];
    #pragma unroll
    for (int mt = 0; mt < 4; mt++)
        #pragma unroll
        for (int nt = 0; nt < 8; nt++)
            #pragma unroll
            for (int q = 0; q < 4; q++) c[mt][nt][q] = 0.f;

    auto load_tile = [&](int kt) {
        if (kt < NKT) {
            const int stage = kt % 3;
            const uint32_t sA = sbase + (uint32_t)stage * GSTAGE;
            const uint32_t sB = sA + 16384u;
            const int reg = kt >> 4;
            const int kk  = (kt & 15) << 6;
            const __nv_bfloat16* Ag = Aregs[reg];
            const __nv_bfloat16* Wg = Wregs[reg];
            #pragma unroll
            for (int i = 0; i < 4; i++) {
                int row = g_r0 + i * 32;
                uint32_t off = (uint32_t)(row * 128 + ((g_c ^ (row & 7)) << 4));
                cp16(sA + off, Ag + (size_t)(bm + row) * 1024 + kk + g_c * 8);
            }
            #pragma unroll
            for (int i = 0; i < 8; i++) {
                int row = g_r0 + i * 32;
                uint32_t off = (uint32_t)(row * 128 + ((g_c ^ (row & 7)) << 4));
                cp16(sB + off, Wg + (size_t)(bn + row) * 1024 + kk + g_c * 8);
            }
        }
        CP_COMMIT();
    };

    load_tile(0);
    load_tile(1);

    for (int kt = 0; kt < NKT; kt++) {
        CP_WAIT1();
        __syncthreads();
        load_tile(kt + 2);

        const uint32_t aB = sbase + (uint32_t)(kt % 3) * GSTAGE;
        const uint32_t bB = aB + 16384u;

        #pragma unroll
        for (int ks = 0; ks < 4; ks++) {
            const int c0 = ks * 2;
            uint32_t a[4][4];
            #pragma unroll
            for (int mt = 0; mt < 4; mt++) {
                int row = m0 + mt * 16 + (phase & 1) * 8 + lrow;
                int ch  = c0 + (phase >> 1);
                ldm_x4(a[mt], aB + (uint32_t)(row * 128 + ((ch ^ (row & 7)) << 4)));
            }
            uint32_t bf[4][4];
            #pragma unroll
            for (int ng = 0; ng < 4; ng++) {
                int row = n0 + ng * 16 + (phase >> 1) * 8 + lrow;
                int ch  = c0 + (phase & 1);
                ldm_x4(bf[ng], bB + (uint32_t)(row * 128 + ((ch ^ (row & 7)) << 4)));
            }
            #pragma unroll
            for (int nt = 0; nt < 8; nt++) {
                uint32_t b0 = bf[nt >> 1][(nt & 1) * 2];
                uint32_t b1 = bf[nt >> 1][(nt & 1) * 2 + 1];
                #pragma unroll
                for (int mt = 0; mt < 4; mt++)
                    MMA16816(c[mt][nt], a[mt], b0, b1);
            }
        }
        __syncthreads();
    }

    // ---- epilogue ----
    #pragma unroll
    for (int mt = 0; mt < 4; mt++) {
        #pragma unroll
        for (int nt = 0; nt < 8; nt++) {
            int r0  = bm + m0 + mt * 16 + qrow;
            int col = bn + n0 + nt * 8 + qk;
            float2 bv = *(const float2*)(bias + col);
            float2 o0, o1;
            o0.x = c[mt][nt][0] + bv.x; o0.y = c[mt][nt][1] + bv.y;
            o1.x = c[mt][nt][2] + bv.x; o1.y = c[mt][nt][3] + bv.y;
            *(float2*)(C + (size_t)r0 * 1024 + col) = o0;
            *(float2*)(C + (size_t)(r0 + 8) * 1024 + col) = o1;
        }
    }
}

// ===================== scores[row] = mean_h ||X[row, h*64:+64]|| ============
__global__ __launch_bounds__(256) void scores_kernel(
    const float* __restrict__ Km, float* __restrict__ scores)
{
    int row  = blockIdx.x * 8 + (threadIdx.x >> 5);
    int lane = threadIdx.x & 31;
    const float* kr = Km + (size_t)row * EE;
    float acc = 0.f;
    #pragma unroll
    for (int h = 0; h < HH; h++) {
        float x0 = kr[h * 64 + lane];
        float x1 = kr[h * 64 + 32 + lane];
        float ss = x0 * x0 + x1 * x1;
        #pragma unroll
        for (int o = 16; o > 0; o >>= 1)
            ss += __shfl_xor_sync(0xffffffffu, ss, o);
        acc += sqrtf(ss);
    }
    if (lane == 0) scores[row] = acc * (1.f / 16.f);
}

// ===================== approx top-kk per batch (1024 threads) ===============
__global__ __launch_bounds__(1024) void topk_kernel(
    const float* __restrict__ scores, int* __restrict__ idxout, int kk)
{
    __shared__ float sv[SS];
    __shared__ float rv[1024];
    __shared__ int   ri[1024];
    const int b = blockIdx.x, t = threadIdx.x;
    for (int i = t; i < SS; i += 1024) sv[i] = scores[b * SS + i];
    __syncthreads();
    for (int l = 0; l < kk; l++) {
        float m = -INFINITY; int a = 0;
        #pragma unroll
        for (int u = 0; u < 8; u++) {
            int i = t + u * 1024;
            float v = sv[i];
            if (v > m) { m = v; a = i; }
        }
        rv[t] = m; ri[t] = a;
        __syncthreads();
        for (int s = 512; s > 0; s >>= 1) {
            if (t < s) {
                float v2 = rv[t + s]; int a2 = ri[t + s];
                if (v2 > rv[t] || (v2 == rv[t] && a2 < ri[t])) { rv[t] = v2; ri[t] = a2; }
            }
            __syncthreads();
        }
        if (t == 0) { idxout[b * kk + l] = ri[0]; sv[ri[0]] = -INFINITY; }
        __syncthreads();
    }
}

// ===================== exact fp32 projection of candidate rows ==============
template<int CPT>
__global__ __launch_bounds__(256) void project_rows(
    const float* __restrict__ X, const float* __restrict__ Wt,
    const float* __restrict__ bias, const int* __restrict__ idx,
    int ncand, float* __restrict__ outp)
{
    __shared__ float xs[NCAND * 32];
    __shared__ float ws[32 * 128];
    const int b = blockIdx.y;
    const int e0 = blockIdx.x * 128;
    const int t = threadIdx.x, tx = t & 31, ty = t >> 5;

    float acc[CPT][4];
    #pragma unroll
    for (int c = 0; c < CPT; c++)
        #pragma unroll
        for (int j = 0; j < 4; j++) acc[c][j] = 0.f;

    for (int kt = 0; kt < EE; kt += 32) {
        __syncthreads();
        for (int u = t; u < ncand * 8; u += 256) {
            int cand = u >> 3, c4 = u & 7;
            int s = idx[b * ncand + cand];
            float4 v = *(const float4*)(X + ((size_t)(b * SS + s)) * EE + kt + c4 * 4);
            *(float4*)(xs + cand * 32 + c4 * 4) = v;
        }
        for (int u = t; u < 1024; u += 256) {
            int e = u >> 3, c4 = u & 7;
            float4 v = *(const float4*)(Wt + (size_t)(e0 + e) * EE + kt + c4 * 4);
            ws[(c4 * 4 + 0) * 128 + e] = v.x;
            ws[(c4 * 4 + 1) * 128 + e] = v.y;
            ws[(c4 * 4 + 2) * 128 + e] = v.z;
            ws[(c4 * 4 + 3) * 128 + e] = v.w;
        }
        __syncthreads();
        #pragma unroll 8
        for (int k = 0; k < 32; k++) {
            float wv[4];
            #pragma unroll
            for (int j = 0; j < 4; j++) wv[j] = ws[k * 128 + tx * 4 + j];
            #pragma unroll
            for (int c = 0; c < CPT; c++) {
                float a = xs[(ty * CPT + c) * 32 + k];
                #pragma unroll
                for (int j = 0; j < 4; j++) acc[c][j] = fmaf(a, wv[j], acc[c][j]);
            }
        }
    }
    #pragma unroll
    for (int c = 0; c < CPT; c++) {
        int cand = ty * CPT + c;
        #pragma unroll
        for (int j = 0; j < 4; j++) {
            int e = e0 + tx * 4 + j;
            outp[((size_t)b * ncand + cand) * EE + e] = acc[c][j] + bias[e];
        }
    }
}

// ===================== exact top-64 among the 96 candidates =================
__global__ __launch_bounds__(128) void topk_refine_kernel(
    const float* __restrict__ scex, const int* __restrict__ idx96,
    int* __restrict__ idxfin, int* __restrict__ candfin)
{
    __shared__ float sv[NCAND];
    __shared__ int   si[NCAND];
    __shared__ float rv[128];
    __shared__ int   rc[128];
    __shared__ int   rs[128];
    const int b = blockIdx.x, t = threadIdx.x;
    if (t < NCAND) { sv[t] = scex[b * NCAND + t]; si[t] = idx96[b * NCAND + t]; }
    __syncthreads();
    for (int l = 0; l < LL; l++) {
        float m = -INFINITY; int c = 0; int sb = 0x7fffffff;
        if (t < NCAND) { m = sv[t]; c = t; sb = si[t]; }
        rv[t] = m; rc[t] = c; rs[t] = sb;
        __syncthreads();
        for (int s = 64; s > 0; s >>= 1) {
            if (t < s) {
                if (rv[t + s] > rv[t] || (rv[t + s] == rv[t] && rs[t + s] < rs[t])) {
                    rv[t] = rv[t + s]; rc[t] = rc[t + s]; rs[t] = rs[t + s];
                }
            }
            __syncthreads();
        }
        if (t == 0) {
            idxfin[b * LL + l] = rs[0];
            candfin[b * LL + l] = rc[0];
            sv[rc[0]] = -INFINITY;
        }
        __syncthreads();
    }
}

// ===================== permute exact rows into [B,H,L,D] ====================
__global__ __launch_bounds__(256) void gatherperm_kernel(
    const float* __restrict__ kex, const float* __restrict__ vex,
    const int* __restrict__ candf,
    float* __restrict__ Ksp, float* __restrict__ Vsp)
{
    int i = blockIdx.x * 256 + threadIdx.x;
    int d = i & 63;
    int l = (i >> 6) & 63;
    int h = (i >> 12) & 15;
    int b = i >> 16;
    int cp = candf[b * LL + l];
    size_t src = ((size_t)b * NCAND + cp) * EE + h * 64 + d;
    Ksp[i] = kex[src];
    Vsp[i] = vex[src];
}

// ===================== attention (R5 proven version) ========================
__global__ __launch_bounds__(64) void attn_kernel(
    const float* __restrict__ Q, const float* __restrict__ Ksp,
    const float* __restrict__ Vsp, float* __restrict__ w_out,
    float* __restrict__ ctx)
{
    __shared__ float Kt[64 * 64];
    __shared__ float Vt[64 * 64];
    __shared__ float sc[64 * 64];

    const int b = blockIdx.z, h = blockIdx.y, chunk = blockIdx.x;
    const int i = threadIdx.x;

    const float* Kg = Ksp + ((size_t)(b * HH + h) << 12);
    const float* Vg = Vsp + ((size_t)(b * HH + h) << 12);
    for (int j = i; j < 1024; j += 64) {
        ((float4*)Kt)[j] = ((const float4*)Kg)[j];
        ((float4*)Vt)[j] = ((const float4*)Vg)[j];
    }
    __syncthreads();

    const int s = chunk * 64 + i;
    const float* qp = Q + ((size_t)(b * SS + s)) * EE + h * 64;
    float4 q4[16];
    #pragma unroll
    for (int j = 0; j < 16; j++) q4[j] = ((const float4*)qp)[j];

    float mx = -INFINITY;
    #pragma unroll 4
    for (int l = 0; l < 64; l++) {
        const float4* kl = (const float4*)(Kt + l * 64);
        float acc = 0.f;
        #pragma unroll
        for (int j = 0; j < 16; j++) {
            float4 kv = kl[j];
            acc = fmaf(q4[j].x, kv.x, acc);
            acc = fmaf(q4[j].y, kv.y, acc);
            acc = fmaf(q4[j].z, kv.z, acc);
            acc = fmaf(q4[j].w, kv.w, acc);
        }
        acc *= 0.125f;
        sc[l * 64 + i] = acc;
        mx = fmaxf(mx, acc);
    }

    float sum = 0.f;
    #pragma unroll 4
    for (int l = 0; l < 64; l++) {
        float e = expf(sc[l * 64 + i] - mx);
        sc[l * 64 + i] = e;
        sum += e;
    }
    const float inv = 1.f / sum;

    float4 c4[16];
    #pragma unroll
    for (int j = 0; j < 16; j++) c4[j] = make_float4(0.f, 0.f, 0.f, 0.f);

    float* wp = w_out + ((size_t)((b * HH + h) * SS + s)) * LL;
    #pragma unroll 2
    for (int l = 0; l < 64; l++) {
        float wl = sc[l * 64 + i] * inv;
        wp[l] = wl;
        const float4* vl = (const float4*)(Vt + l * 64);
        #pragma unroll
        for (int j = 0; j < 16; j++) {
            float4 vv = vl[j];
            c4[j].x = fmaf(wl, vv.x, c4[j].x);
            c4[j].y = fmaf(wl, vv.y, c4[j].y);
            c4[j].z = fmaf(wl, vv.z, c4[j].z);
            c4[j].w = fmaf(wl, vv.w, c4[j].w);
        }
    }

    float* cp = ctx + ((size_t)(b * SS + s)) * EE + h * 64;
    #pragma unroll
    for (int j = 0; j < 16; j++) ((float4*)cp)[j] = c4[j];
}

// ===================== launch ===============================================
extern "C" void kernel_launch(void* const* d_in, const int* in_sizes, int n_in,
                              void* d_out, int out_size)
{
    const float* query = (const float*)d_in[0];
    const float* key   = (const float*)d_in[1];
    const float* value = (const float*)d_in[2];
    const float* Wq = (const float*)d_in[3];
    const float* bq = (const float*)d_in[4];
    const float* Wk = (const float*)d_in[5];
    const float* bk = (const float*)d_in[6];
    const float* Wv = (const float*)d_in[7];
    const float* bv = (const float*)d_in[8];
    const float* Wo = (const float*)d_in[9];
    const float* bo = (const float*)d_in[10];

    float* out  = (float*)d_out;
    float* wout = out + MSZ;

    float *pQ, *pK, *pC, *pScores, *pKex, *pVex, *pScex, *pKsp, *pVsp;
    __nv_bfloat16 *pAqhi, *pAqmid, *pAkhi, *pAkmid;
    __nv_bfloat16 *pWqhi, *pWqmid, *pWkhi, *pWkmid, *pWohi, *pWomid;
    int *pIdx96, *pIdxf, *pCandf;
    cudaGetSymbolAddress((void**)&pQ, g_Q);
    cudaGetSymbolAddress((void**)&pK, g_K);
    cudaGetSymbolAddress((void**)&pC, g_ctx);
    cudaGetSymbolAddress((void**)&pAqhi, g_Aqhi);
    cudaGetSymbolAddress((void**)&pAqmid, g_Aqmid);
    cudaGetSymbolAddress((void**)&pAkhi, g_Akhi);
    cudaGetSymbolAddress((void**)&pAkmid, g_Akmid);
    cudaGetSymbolAddress((void**)&pWqhi, g_Wqhi);
    cudaGetSymbolAddress((void**)&pWqmid, g_Wqmid);
    cudaGetSymbolAddress((void**)&pWkhi, g_Wkhi);
    cudaGetSymbolAddress((void**)&pWkmid, g_Wkmid);
    cudaGetSymbolAddress((void**)&pWohi, g_Wohi);
    cudaGetSymbolAddress((void**)&pWomid, g_Womid);
    cudaGetSymbolAddress((void**)&pScores, g_scores);
    cudaGetSymbolAddress((void**)&pIdx96, g_idx96);
    cudaGetSymbolAddress((void**)&pKex, g_kex);
    cudaGetSymbolAddress((void**)&pVex, g_vex);
    cudaGetSymbolAddress((void**)&pScex, g_scex);
    cudaGetSymbolAddress((void**)&pIdxf, g_idxf);
    cudaGetSymbolAddress((void**)&pCandf, g_candf);
    cudaGetSymbolAddress((void**)&pKsp, g_Ksp);
    cudaGetSymbolAddress((void**)&pVsp, g_Vsp);

    cudaFuncSetAttribute(mma_gemm<48>, cudaFuncAttributeMaxDynamicSharedMemorySize, GEMM_SMEM);
    cudaFuncSetAttribute(mma_gemm<16>, cudaFuncAttributeMaxDynamicSharedMemorySize, GEMM_SMEM);

    const int n4m = (int)(MSZ / 4);
    const int n4w = EE * EE / 4;
    dim3 ggrid(4, 256);

    // launches 1-5: all weight splits + input splits (makes launch 6 = GEMM for ncu)
    split2_kernel<<<n4w / 256, 256>>>(Wq, pWqhi, pWqmid, n4w);
    split2_kernel<<<n4w / 256, 256>>>(Wk, pWkhi, pWkmid, n4w);
    split2_kernel<<<n4w / 256, 256>>>(Wo, pWohi, pWomid, n4w);
    split2_kernel<<<n4m / 256, 256>>>(query, pAqhi, pAqmid, n4m);
    split2_kernel<<<n4m / 256, 256>>>(key,   pAkhi, pAkmid, n4m);

    // launch 6: Q GEMM (3-product) — ncu -s 5 -c 1 captures this
    mma_gemm<48><<<ggrid, 256, GEMM_SMEM>>>(pAqhi, pAqmid, pWqhi, pWqmid, bq, pQ);

    // K GEMM: single product (selection-only accuracy; protected by exact rescore)
    mma_gemm<16><<<ggrid, 256, GEMM_SMEM>>>(pAkhi, pAkmid, pWkhi, pWkmid, bk, pK);

    // approx scores -> top-96 candidates
    scores_kernel<<<MROWS / 8, 256>>>(pK, pScores);
    topk_kernel<<<BB, 1024>>>(pScores, pIdx96, NCAND);

    // exact fp32 K/V rows at candidates, exact scores, exact top-64
    dim3 pgrid(8, BB);
    project_rows<12><<<pgrid, 256>>>(key,   Wk, bk, pIdx96, NCAND, pKex);
    project_rows<12><<<pgrid, 256>>>(value, Wv, bv, pIdx96, NCAND, pVex);
    scores_kernel<<<(BB * NCAND) / 8, 256>>>(pKex, pScex);
    topk_refine_kernel<<<BB, 128>>>(pScex, pIdx96, pIdxf, pCandf);
    gatherperm_kernel<<<(BB * HH * LL * DD) / 256, 256>>>(pKex, pVex, pCandf, pKsp, pVsp);

    // attention
    dim3 agrid(SS / 64, HH, BB);
    attn_kernel<<<agrid, 64>>>(pQ, pKsp, pVsp, wout, pC);

    // out = ctx @ Wo^T + bo (3-product)
    split2_kernel<<<n4m / 256, 256>>>(pC, pAqhi, pAqmid, n4m);
    mma_gemm<48><<<ggrid, 256, GEMM_SMEM>>>(pAqhi, pAqmid, pWohi, pWomid, bo, out);
}